// round 5
// baseline (speedup 1.0000x reference)
#include <cuda_runtime.h>

// Node2VecModel: N=6, EMB=32. One latency-bound kernel, warp-specialized:
//   warps 0-5  (bar 1): energy MLP -> out[0..5]
//   warps 6-11 (bar 2): path logits -> gumbel-max walk -> out[6..12]
// R5: float4 smem staging of weights (kills 64-LDG/thread issue streams),
//     drop log_softmax (row constant cancels in argmax), fuse h2+head with
//     a warp shuffle reduction (one barrier fewer per chain).

#define NN   6
#define EMBD 32
#define H1   64
#define H2   32

__device__ __forceinline__ void tf2x32(unsigned k0, unsigned k1,
                                       unsigned x0, unsigned x1,
                                       unsigned &o0, unsigned &o1) {
    unsigned ks2 = k0 ^ k1 ^ 0x1BD11BDAu;
    x0 += k0; x1 += k1;
#define TF_RND(r) { x0 += x1; x1 = (x1 << (r)) | (x1 >> (32 - (r))); x1 ^= x0; }
    TF_RND(13) TF_RND(15) TF_RND(26) TF_RND(6)
    x0 += k1;  x1 += ks2 + 1u;
    TF_RND(17) TF_RND(29) TF_RND(16) TF_RND(24)
    x0 += ks2; x1 += k0 + 2u;
    TF_RND(13) TF_RND(15) TF_RND(26) TF_RND(6)
    x0 += k0;  x1 += k1 + 3u;
    TF_RND(17) TF_RND(29) TF_RND(16) TF_RND(24)
    x0 += k1;  x1 += ks2 + 4u;
    TF_RND(13) TF_RND(15) TF_RND(26) TF_RND(6)
    x0 += ks2; x1 += k0 + 5u;
#undef TF_RND
    o0 = x0; o1 = x1;
}

// JAX uniform(tiny,1) fp32 -> gumbel. (1-tiny) rounds to 1.0f => u = max(tiny, f+tiny).
__device__ __forceinline__ float gumbel_from_bits(unsigned b) {
    const float tiny = 1.1754943508222875e-38f;
    float f = __uint_as_float((b >> 9) | 0x3f800000u) - 1.0f;
    float u = fmaxf(__fadd_rn(f, tiny), tiny);
    return -logf(-logf(u));
}

#define BARSYNC(id) asm volatile("bar.sync %0, 192;" :: "r"(id) : "memory")

__global__ __launch_bounds__(384, 1)
void node2vec_kernel(const float* __restrict__ x,
                     const float* __restrict__ fc1_w, const float* __restrict__ fc1_b,
                     const float* __restrict__ fc2_w, const float* __restrict__ fc2_b,
                     const float* __restrict__ fc3_w, const float* __restrict__ fc3_b,
                     const float* __restrict__ pw,    const float* __restrict__ pb,
                     float* __restrict__ out) {
    __shared__ float sx[NN * EMBD];          // 768 B
    __shared__ float w1s[EMBD * H1];         // 8 KB  [k][j] row-major copy
    __shared__ float w2s[H1 * H2];           // 8 KB  [k][j] row-major copy
    __shared__ float h1s[NN][H1];
    __shared__ float logits[NN][NN];         // raw logits (no softmax needed)
    __shared__ float g[NN - 1][NN];

    int tid = threadIdx.x;

    if (tid < 192) {
        // ================= ENERGY CHAIN (warps 0-5, bar.sync 1) =================
        int j1 = tid & 63, r1 = tid >> 6;           // h1 elems (r1,j1),(r1+3,j1)
        int i2 = tid >> 5, j2 = tid & 31;           // h2 elem (i2,j2); warp i2

        // scalar per-thread params (latency overlapped with staging)
        float b1v = fc1_b[j1];
        float b2v = fc2_b[j2];
        float w3v = fc3_w[j2];
        float b3v = fc3_b[0];

        // float4 staging: fc1_w, fc2_w = 512 float4 each; x = 48 float4
        {
            const float4* f1 = (const float4*)fc1_w;
            const float4* f2 = (const float4*)fc2_w;
            float4* d1 = (float4*)w1s;
            float4* d2 = (float4*)w2s;
            d1[tid] = f1[tid];            d2[tid] = f2[tid];
            d1[tid + 192] = f1[tid + 192]; d2[tid + 192] = f2[tid + 192];
            if (tid < 128) { d1[tid + 384] = f1[tid + 384]; d2[tid + 384] = f2[tid + 384]; }
            if (tid < 48)  ((float4*)sx)[tid] = ((const float4*)x)[tid];
        }
        BARSYNC(1);

        // h1 = relu(x @ fc1_w + b1): 2 rows per thread, independent accumulators
        {
            float a0 = b1v, a1 = b1v;
            #pragma unroll
            for (int k = 0; k < EMBD; k++) {
                float w = w1s[k * H1 + j1];
                a0 += sx[r1 * EMBD + k]       * w;
                a1 += sx[(r1 + 3) * EMBD + k] * w;
            }
            h1s[r1][j1]     = fmaxf(a0, 0.0f);
            h1s[r1 + 3][j1] = fmaxf(a1, 0.0f);
        }
        BARSYNC(1);

        // h2 + energy head fused: warp i2 owns row i2; lane j2 computes h2[i2][j2],
        // multiplies by fc3_w[j2], warp-reduces, lane 0 applies softplus.
        {
            float c0 = 0.f, c1 = 0.f, c2 = 0.f, c3 = 0.f;
            #pragma unroll
            for (int k = 0; k < H1; k += 4) {
                c0 += h1s[i2][k]     * w2s[k * H2 + j2];
                c1 += h1s[i2][k + 1] * w2s[(k + 1) * H2 + j2];
                c2 += h1s[i2][k + 2] * w2s[(k + 2) * H2 + j2];
                c3 += h1s[i2][k + 3] * w2s[(k + 3) * H2 + j2];
            }
            float rel = fmaxf(b2v + ((c0 + c1) + (c2 + c3)), 0.0f);
            float p = rel * w3v;
            #pragma unroll
            for (int off = 16; off; off >>= 1)
                p += __shfl_xor_sync(0xffffffffu, p, off);
            if (j2 == 0) {
                float acc = p + b3v;
                out[i2] = fmaxf(acc, 0.0f) + log1pf(expf(-fabsf(acc)));  // softplus
            }
        }
    } else {
        // ================= PATH CHAIN (warps 6-11, bar.sync 2) =================
        int t = tid - 192;

        // endpoints are fixed: write early from an idle thread
        if (t == 36) { out[NN] = 0.0f; out[2 * NN] = 0.0f; }

        // gumbels (warp 11, 30 threads): path-independent, overlap with LDGs
        if (t >= 160 && t < 160 + (NN - 1) * NN) {
            int u = t - 160, step = u / NN, j = u % NN;
            unsigned k0, k1, o0, o1;
            tf2x32(0u, 42u, 0u, (unsigned)step, k0, k1);   // split(key(42),5)[step]
            tf2x32(k0, k1, 0u, (unsigned)j, o0, o1);       // random_bits xor-fold
            g[step][j] = gumbel_from_bits(o0 ^ o1);
        }

        // raw logits = x @ path_fc_w + path_fc_b (36 threads).
        // log_softmax is skipped: per-row constant cancels in the argmax below.
        if (t < NN * NN) {
            int i = t / NN, j = t % NN;
            float acc = pb[j];
            #pragma unroll
            for (int k = 0; k < EMBD; k++)
                acc += x[i * EMBD + k] * pw[k * NN + j];
            logits[i][j] = acc;
        }
        BARSYNC(2);

        // serial gumbel-max walk (thread 192)
        if (t == 0) {
            bool mask[NN];
            mask[0] = false;
            #pragma unroll
            for (int j = 1; j < NN; j++) mask[j] = true;

            int cur = 0;
            #pragma unroll
            for (int step = 0; step < NN - 1; step++) {
                float best = -__int_as_float(0x7f800000);
                int bestj = 0;
                bool have = false;
                #pragma unroll
                for (int j = 0; j < NN; j++) {
                    if (!mask[j]) continue;          // where(mask,.,-inf)+g = -inf
                    float v = logits[cur][j] + g[step][j];
                    if (!have || v > best) { best = v; bestj = j; have = true; }
                }
                cur = bestj;
                mask[bestj] = false;
                out[NN + 1 + step] = (float)bestj;
            }
        }
    }
}

extern "C" void kernel_launch(void* const* d_in, const int* in_sizes, int n_in,
                              void* d_out, int out_size) {
    const float* x     = (const float*)d_in[0];
    // d_in[1] = path (int32, unused by the forward outputs)
    const float* fc1_w = (const float*)d_in[2];
    const float* fc1_b = (const float*)d_in[3];
    const float* fc2_w = (const float*)d_in[4];
    const float* fc2_b = (const float*)d_in[5];
    const float* fc3_w = (const float*)d_in[6];
    const float* fc3_b = (const float*)d_in[7];
    const float* pw    = (const float*)d_in[8];
    const float* pb    = (const float*)d_in[9];
    float* out = (float*)d_out;

    node2vec_kernel<<<1, 384>>>(x, fc1_w, fc1_b, fc2_w, fc2_b,
                                fc3_w, fc3_b, pw, pb, out);
}

// round 6
// speedup vs baseline: 1.0435x; 1.0435x over previous
#include <cuda_runtime.h>

// Node2VecModel: N=6, EMB=32. One latency-bound kernel, warp-specialized:
//   warps 0-5  (bar 1): energy MLP -> out[0..5]   (2 barriers total)
//   warps 6-11 (bar 2): raw path logits -> gumbel-max walk -> out[6..12]
// R6 = R4's register-prefetch weights (measured faster than smem staging)
//      + R5's log_softmax elimination + fused h2/head shuffle reduction.

#define NN   6
#define EMBD 32
#define H1   64
#define H2   32

__device__ __forceinline__ void tf2x32(unsigned k0, unsigned k1,
                                       unsigned x0, unsigned x1,
                                       unsigned &o0, unsigned &o1) {
    unsigned ks2 = k0 ^ k1 ^ 0x1BD11BDAu;
    x0 += k0; x1 += k1;
#define TF_RND(r) { x0 += x1; x1 = (x1 << (r)) | (x1 >> (32 - (r))); x1 ^= x0; }
    TF_RND(13) TF_RND(15) TF_RND(26) TF_RND(6)
    x0 += k1;  x1 += ks2 + 1u;
    TF_RND(17) TF_RND(29) TF_RND(16) TF_RND(24)
    x0 += ks2; x1 += k0 + 2u;
    TF_RND(13) TF_RND(15) TF_RND(26) TF_RND(6)
    x0 += k0;  x1 += k1 + 3u;
    TF_RND(17) TF_RND(29) TF_RND(16) TF_RND(24)
    x0 += k1;  x1 += ks2 + 4u;
    TF_RND(13) TF_RND(15) TF_RND(26) TF_RND(6)
    x0 += ks2; x1 += k0 + 5u;
#undef TF_RND
    o0 = x0; o1 = x1;
}

// JAX uniform(tiny,1) fp32 -> gumbel. (1-tiny) rounds to 1.0f => u = max(tiny, f+tiny).
__device__ __forceinline__ float gumbel_from_bits(unsigned b) {
    const float tiny = 1.1754943508222875e-38f;
    float f = __uint_as_float((b >> 9) | 0x3f800000u) - 1.0f;
    float u = fmaxf(__fadd_rn(f, tiny), tiny);
    return -logf(-logf(u));
}

#define BARSYNC(id) asm volatile("bar.sync %0, 192;" :: "r"(id) : "memory")

__global__ __launch_bounds__(384, 1)
void node2vec_kernel(const float* __restrict__ x,
                     const float* __restrict__ fc1_w, const float* __restrict__ fc1_b,
                     const float* __restrict__ fc2_w, const float* __restrict__ fc2_b,
                     const float* __restrict__ fc3_w, const float* __restrict__ fc3_b,
                     const float* __restrict__ pw,    const float* __restrict__ pb,
                     float* __restrict__ out) {
    __shared__ float sxE[NN * EMBD];
    __shared__ float h1s[NN][H1];
    __shared__ float logits[NN][NN];         // raw logits (softmax cancels in argmax)
    __shared__ float g[NN - 1][NN];

    int tid = threadIdx.x;

    if (tid < 192) {
        // ================= ENERGY CHAIN (warps 0-5, bar.sync 1) =================
        int j1 = tid & 63, r1 = tid >> 6;          // h1 elems (r1,j1),(r1+3,j1)
        int i2 = tid >> 5, j2 = tid & 31;          // h2 elem (i2,j2); warp i2 = row i2

        // register prefetch: all LDGs issued before the first barrier
        float w1[EMBD];
        #pragma unroll
        for (int k = 0; k < EMBD; k++) w1[k] = fc1_w[k * H1 + j1];
        float b1v = fc1_b[j1];

        float w2[H1];
        #pragma unroll
        for (int k = 0; k < H1; k++) w2[k] = fc2_w[k * H2 + j2];
        float b2v = fc2_b[j2];
        float w3v = fc3_w[j2];
        float b3v = fc3_b[0];

        sxE[tid] = x[tid];                          // stage x (192 floats)
        BARSYNC(1);

        // h1 = relu(x @ fc1_w + b1): 2 rows per thread, independent accumulators
        {
            float a0 = b1v, a1 = b1v;
            #pragma unroll
            for (int k = 0; k < EMBD; k++) {
                a0 += sxE[r1 * EMBD + k]       * w1[k];
                a1 += sxE[(r1 + 3) * EMBD + k] * w1[k];
            }
            h1s[r1][j1]     = fmaxf(a0, 0.0f);
            h1s[r1 + 3][j1] = fmaxf(a1, 0.0f);
        }
        BARSYNC(1);

        // h2 + energy head fused: warp i2 owns row i2; lane j2 computes h2[i2][j2],
        // scales by fc3_w[j2], warp-reduces, lane 0 applies softplus and stores.
        {
            float c0 = 0.f, c1 = 0.f, c2 = 0.f, c3 = 0.f;
            #pragma unroll
            for (int k = 0; k < H1; k += 4) {
                c0 += h1s[i2][k]     * w2[k];
                c1 += h1s[i2][k + 1] * w2[k + 1];
                c2 += h1s[i2][k + 2] * w2[k + 2];
                c3 += h1s[i2][k + 3] * w2[k + 3];
            }
            float rel = fmaxf(b2v + ((c0 + c1) + (c2 + c3)), 0.0f);
            float p = rel * w3v;
            #pragma unroll
            for (int off = 16; off; off >>= 1)
                p += __shfl_xor_sync(0xffffffffu, p, off);
            if (j2 == 0) {
                float acc = p + b3v;
                out[i2] = fmaxf(acc, 0.0f) + log1pf(expf(-fabsf(acc)));  // softplus
            }
        }
    } else {
        // ================= PATH CHAIN (warps 6-11, bar.sync 2) =================
        int t = tid - 192;

        // fixed endpoints: write early from an otherwise-idle thread
        if (t == 36) { out[NN] = 0.0f; out[2 * NN] = 0.0f; }

        // gumbels (warp 11, 30 threads): path-independent, overlap with LDGs
        if (t >= 160 && t < 160 + (NN - 1) * NN) {
            int u = t - 160, step = u / NN, j = u % NN;
            unsigned k0, k1, o0, o1;
            tf2x32(0u, 42u, 0u, (unsigned)step, k0, k1);   // split(key(42),5)[step]
            tf2x32(k0, k1, 0u, (unsigned)j, o0, o1);       // random_bits xor-fold
            g[step][j] = gumbel_from_bits(o0 ^ o1);
        }

        // raw logits = x @ path_fc_w + path_fc_b (36 threads).
        // log_softmax skipped: per-row constant cancels in the argmax below.
        if (t < NN * NN) {
            int i = t / NN, j = t % NN;
            float acc = pb[j];
            #pragma unroll
            for (int k = 0; k < EMBD; k++)
                acc += x[i * EMBD + k] * pw[k * NN + j];
            logits[i][j] = acc;
        }
        BARSYNC(2);

        // serial gumbel-max walk (thread 192)
        if (t == 0) {
            bool mask[NN];
            mask[0] = false;
            #pragma unroll
            for (int j = 1; j < NN; j++) mask[j] = true;

            int cur = 0;
            #pragma unroll
            for (int step = 0; step < NN - 1; step++) {
                float best = -__int_as_float(0x7f800000);
                int bestj = 0;
                bool have = false;
                #pragma unroll
                for (int j = 0; j < NN; j++) {
                    if (!mask[j]) continue;          // where(mask,.,-inf)+g = -inf
                    float v = logits[cur][j] + g[step][j];
                    if (!have || v > best) { best = v; bestj = j; have = true; }
                }
                cur = bestj;
                mask[bestj] = false;
                out[NN + 1 + step] = (float)bestj;
            }
        }
    }
}

extern "C" void kernel_launch(void* const* d_in, const int* in_sizes, int n_in,
                              void* d_out, int out_size) {
    const float* x     = (const float*)d_in[0];
    // d_in[1] = path (int32, unused by the forward outputs)
    const float* fc1_w = (const float*)d_in[2];
    const float* fc1_b = (const float*)d_in[3];
    const float* fc2_w = (const float*)d_in[4];
    const float* fc2_b = (const float*)d_in[5];
    const float* fc3_w = (const float*)d_in[6];
    const float* fc3_b = (const float*)d_in[7];
    const float* pw    = (const float*)d_in[8];
    const float* pb    = (const float*)d_in[9];
    float* out = (float*)d_out;

    node2vec_kernel<<<1, 384>>>(x, fc1_w, fc1_b, fc2_w, fc2_b,
                                fc3_w, fc3_b, pw, pb, out);
}